// round 1
// baseline (speedup 1.0000x reference)
#include <cuda_runtime.h>
#include <cstdint>

// Problem constants (fixed by the dataset)
#define NWIN   65536      // B * NW = 2048 * 32 query windows
#define DIM    128        // window / codebook dim
#define KCB    2048       // codebook entries
#define MT     128        // windows per block
#define KT     128        // codebook entries per k-tile
#define NKT    (KCB / KT) // 16 k-tiles

// Precomputed ||c_k||^2
__device__ float g_cnorm[KCB];

// ---------------------------------------------------------------------------
// Kernel 1: codebook squared norms. One warp per codebook row.
// ---------------------------------------------------------------------------
__global__ void cnorm_kernel(const float* __restrict__ cb) {
    int warp = (blockIdx.x * blockDim.x + threadIdx.x) >> 5;
    int lane = threadIdx.x & 31;
    if (warp >= KCB) return;
    const float4* row = (const float4*)(cb + (size_t)warp * DIM);
    float4 v = row[lane];                       // 32 lanes x float4 = 128 floats
    float s = v.x * v.x + v.y * v.y + v.z * v.z + v.w * v.w;
    #pragma unroll
    for (int o = 16; o; o >>= 1) s += __shfl_xor_sync(0xFFFFFFFFu, s, o);
    if (lane == 0) g_cnorm[warp] = s;
}

// packed f32x2 FMA: acc = a * b + acc (elementwise on the two packed floats)
__device__ __forceinline__ void fma_f32x2(unsigned long long& acc,
                                          unsigned long long a,
                                          unsigned long long b) {
    asm("fma.rn.f32x2 %0, %1, %2, %0;" : "+l"(acc) : "l"(a), "l"(b));
}

__device__ __forceinline__ float pair_sum(unsigned long long p) {
    float lo = __uint_as_float((unsigned)(p & 0xFFFFFFFFull));
    float hi = __uint_as_float((unsigned)(p >> 32));
    return lo + hi;
}

// ---------------------------------------------------------------------------
// Kernel 2: fused score-GEMM + argmin + gather.
//   Block: 128 windows x all 2048 codebook entries (16 k-tiles of 128).
//   256 threads as (tx in [0,16), ty in [0,16)); each thread: 8 m-rows x 8 k-cols.
//   smem tiles stored d2-major as packed float2 (ull) so inner-loop frag loads
//   are LDS.128. b-frag k-columns strided: k(j) = 32*(j/2) + 2*tx + (j&1) so a
//   warp's simultaneous LDS.128s cover a contiguous 256B span (conflict-free).
// ---------------------------------------------------------------------------
__global__ __launch_bounds__(256, 1)
void vq_kernel(const float* __restrict__ ze,
               const float* __restrict__ cb,
               float* __restrict__ out) {
    extern __shared__ unsigned long long smem[];
    unsigned long long* zs = smem;             // [64][128] packed f32x2: (d2, m)
    unsigned long long* cs = smem + 64 * 128;  // [64][128] packed f32x2: (d2, k)

    const int tid = threadIdx.x;
    const int tx  = tid & 15;
    const int ty  = tid >> 4;
    const int m0  = blockIdx.x * MT;

    // --- load z tile (fully contiguous 128*128 floats) transposed into zs ---
    {
        const unsigned long long* zg = (const unsigned long long*)(ze + (size_t)m0 * DIM);
        #pragma unroll
        for (int i = tid; i < MT * 64; i += 256) {
            int m = i >> 6, d2 = i & 63;
            zs[d2 * 128 + m] = zg[i];
        }
    }

    float minv[8];
    int   mini[8];
    #pragma unroll
    for (int i = 0; i < 8; i++) { minv[i] = 3.4e38f; mini[i] = 0; }

    for (int kt = 0; kt < NKT; kt++) {
        __syncthreads();
        const unsigned long long* cg =
            (const unsigned long long*)(cb + (size_t)kt * KT * DIM);
        #pragma unroll
        for (int i = tid; i < KT * 64; i += 256) {
            int k = i >> 6, d2 = i & 63;
            cs[d2 * 128 + k] = cg[i];
        }
        __syncthreads();

        unsigned long long acc[8][8];
        #pragma unroll
        for (int i = 0; i < 8; i++)
            #pragma unroll
            for (int j = 0; j < 8; j++) acc[i][j] = 0ull;

        #pragma unroll 2
        for (int d2 = 0; d2 < 64; d2++) {
            unsigned long long a[8], b[8];
            const ulonglong2* za = (const ulonglong2*)(zs + d2 * 128 + ty * 8);
            const ulonglong2* cbase = (const ulonglong2*)(cs + d2 * 128);
            #pragma unroll
            for (int c = 0; c < 4; c++) {
                ulonglong2 av = za[c];
                a[2 * c] = av.x; a[2 * c + 1] = av.y;
                ulonglong2 bv = cbase[tx + 16 * c];
                b[2 * c] = bv.x; b[2 * c + 1] = bv.y;
            }
            #pragma unroll
            for (int i = 0; i < 8; i++)
                #pragma unroll
                for (int j = 0; j < 8; j++)
                    fma_f32x2(acc[i][j], a[i], b[j]);
        }

        // epilogue for this k-tile: score = ||c||^2 - 2*dot, running argmin
        #pragma unroll
        for (int j = 0; j < 8; j++) {
            int k = kt * KT + 32 * (j >> 1) + 2 * tx + (j & 1);
            float cn = g_cnorm[k];
            #pragma unroll
            for (int i = 0; i < 8; i++) {
                float s = fmaf(-2.0f, pair_sum(acc[i][j]), cn);
                if (s < minv[i]) { minv[i] = s; mini[i] = k; }
            }
        }
    }

    // --- cross-thread argmin reduction (16 tx partials per m-row) ---
    __syncthreads();
    float* rv = (float*)cs;                 // [16][132] (padded stride)
    int*   ri = (int*)(rv + 16 * 132);      // [16][132]
    #pragma unroll
    for (int i = 0; i < 8; i++) {
        int m = ty * 8 + i;
        rv[tx * 132 + m] = minv[i];
        ri[tx * 132 + m] = mini[i];
    }
    __syncthreads();
    int* fidx = (int*)zs;                   // final index per m-row
    if (tid < MT) {
        int m = tid;
        float bv = rv[m];
        int   bi = ri[m];
        #pragma unroll
        for (int t = 1; t < 16; t++) {
            float v = rv[t * 132 + m];
            int  id = ri[t * 132 + m];
            if (v < bv || (v == bv && id < bi)) { bv = v; bi = id; }
        }
        fidx[m] = bi;
    }
    __syncthreads();

    // --- gather + write output (codebook is L2-hot, 1 MB total) ---
    const float4* cb4 = (const float4*)cb;
    float4* out4 = (float4*)out;
    #pragma unroll
    for (int i = tid; i < MT * (DIM / 4); i += 256) {
        int m = i >> 5;                     // DIM/4 = 32 float4 per row
        int c = i & 31;
        int idx = fidx[m];
        out4[(size_t)(m0 + m) * 32 + c] = cb4[(size_t)idx * 32 + c];
    }
}

// ---------------------------------------------------------------------------
extern "C" void kernel_launch(void* const* d_in, const int* in_sizes, int n_in,
                              void* d_out, int out_size) {
    const float* ze = (const float*)d_in[0];   // [2048, 4096] == [65536, 128]
    const float* cb = (const float*)d_in[1];   // [2048, 128]
    float* out = (float*)d_out;                // [65536, 128]

    (void)in_sizes; (void)n_in; (void)out_size;

    cudaFuncSetAttribute(vq_kernel,
                         cudaFuncAttributeMaxDynamicSharedMemorySize,
                         131072);

    cnorm_kernel<<<KCB / 8, 256>>>(cb);
    vq_kernel<<<NWIN / MT, 256, 131072>>>(ze, cb, out);
}

// round 2
// speedup vs baseline: 1.0010x; 1.0010x over previous
#include <cuda_runtime.h>
#include <cstdint>

// Problem constants (fixed by the dataset)
#define NWIN   65536      // B * NW = 2048 * 32 query windows
#define DIM    128        // window / codebook dim
#define KCB    2048       // codebook entries
#define MT     128        // windows per block
#define KT     128        // codebook entries per k-tile
#define NKT    (KCB / KT) // 16 k-tiles

// Precomputed ||c_k||^2
__device__ float g_cnorm[KCB];

// ---------------------------------------------------------------------------
// Kernel 1: codebook squared norms. One warp per codebook row.
// ---------------------------------------------------------------------------
__global__ void cnorm_kernel(const float* __restrict__ cb) {
    int warp = (blockIdx.x * blockDim.x + threadIdx.x) >> 5;
    int lane = threadIdx.x & 31;
    if (warp >= KCB) return;
    const float4* row = (const float4*)(cb + (size_t)warp * DIM);
    float4 v = row[lane];                       // 32 lanes x float4 = 128 floats
    float s = v.x * v.x + v.y * v.y + v.z * v.z + v.w * v.w;
    #pragma unroll
    for (int o = 16; o; o >>= 1) s += __shfl_xor_sync(0xFFFFFFFFu, s, o);
    if (lane == 0) g_cnorm[warp] = s;
}

// packed f32x2 FMA: acc = a * b + acc (elementwise on the two packed floats)
__device__ __forceinline__ void fma_f32x2(unsigned long long& acc,
                                          unsigned long long a,
                                          unsigned long long b) {
    asm("fma.rn.f32x2 %0, %1, %2, %0;" : "+l"(acc) : "l"(a), "l"(b));
}

__device__ __forceinline__ float pair_sum(unsigned long long p) {
    float lo = __uint_as_float((unsigned)(p & 0xFFFFFFFFull));
    float hi = __uint_as_float((unsigned)(p >> 32));
    return lo + hi;
}

// ---------------------------------------------------------------------------
// Kernel 2: fused score-GEMM + argmin + gather.
//   Block: 128 windows x all 2048 codebook entries (16 k-tiles of 128).
//   256 threads as (tx in [0,16), ty in [0,16)); each thread: 8 m-rows x 8 k-cols.
//   smem tiles stored d2-major as packed float2 (ull) so inner-loop frag loads
//   are LDS.128. b-frag k-columns strided: k(j) = 32*(j/2) + 2*tx + (j&1) so a
//   warp's simultaneous LDS.128s cover a contiguous 256B span (conflict-free).
// ---------------------------------------------------------------------------
__global__ __launch_bounds__(256, 1)
void vq_kernel(const float* __restrict__ ze,
               const float* __restrict__ cb,
               float* __restrict__ out) {
    extern __shared__ unsigned long long smem[];
    unsigned long long* zs = smem;             // [64][128] packed f32x2: (d2, m)
    unsigned long long* cs = smem + 64 * 128;  // [64][128] packed f32x2: (d2, k)

    const int tid = threadIdx.x;
    const int tx  = tid & 15;
    const int ty  = tid >> 4;
    const int m0  = blockIdx.x * MT;

    // --- load z tile (fully contiguous 128*128 floats) transposed into zs ---
    {
        const unsigned long long* zg = (const unsigned long long*)(ze + (size_t)m0 * DIM);
        #pragma unroll
        for (int i = tid; i < MT * 64; i += 256) {
            int m = i >> 6, d2 = i & 63;
            zs[d2 * 128 + m] = zg[i];
        }
    }

    float minv[8];
    int   mini[8];
    #pragma unroll
    for (int i = 0; i < 8; i++) { minv[i] = 3.4e38f; mini[i] = 0; }

    for (int kt = 0; kt < NKT; kt++) {
        __syncthreads();
        const unsigned long long* cg =
            (const unsigned long long*)(cb + (size_t)kt * KT * DIM);
        #pragma unroll
        for (int i = tid; i < KT * 64; i += 256) {
            int k = i >> 6, d2 = i & 63;
            cs[d2 * 128 + k] = cg[i];
        }
        __syncthreads();

        unsigned long long acc[8][8];
        #pragma unroll
        for (int i = 0; i < 8; i++)
            #pragma unroll
            for (int j = 0; j < 8; j++) acc[i][j] = 0ull;

        #pragma unroll 2
        for (int d2 = 0; d2 < 64; d2++) {
            unsigned long long a[8], b[8];
            const ulonglong2* za = (const ulonglong2*)(zs + d2 * 128 + ty * 8);
            const ulonglong2* cbase = (const ulonglong2*)(cs + d2 * 128);
            #pragma unroll
            for (int c = 0; c < 4; c++) {
                ulonglong2 av = za[c];
                a[2 * c] = av.x; a[2 * c + 1] = av.y;
                ulonglong2 bv = cbase[tx + 16 * c];
                b[2 * c] = bv.x; b[2 * c + 1] = bv.y;
            }
            #pragma unroll
            for (int i = 0; i < 8; i++)
                #pragma unroll
                for (int j = 0; j < 8; j++)
                    fma_f32x2(acc[i][j], a[i], b[j]);
        }

        // epilogue for this k-tile: score = ||c||^2 - 2*dot, running argmin
        #pragma unroll
        for (int j = 0; j < 8; j++) {
            int k = kt * KT + 32 * (j >> 1) + 2 * tx + (j & 1);
            float cn = g_cnorm[k];
            #pragma unroll
            for (int i = 0; i < 8; i++) {
                float s = fmaf(-2.0f, pair_sum(acc[i][j]), cn);
                if (s < minv[i]) { minv[i] = s; mini[i] = k; }
            }
        }
    }

    // --- cross-thread argmin reduction (16 tx partials per m-row) ---
    __syncthreads();
    float* rv = (float*)cs;                 // [16][132] (padded stride)
    int*   ri = (int*)(rv + 16 * 132);      // [16][132]
    #pragma unroll
    for (int i = 0; i < 8; i++) {
        int m = ty * 8 + i;
        rv[tx * 132 + m] = minv[i];
        ri[tx * 132 + m] = mini[i];
    }
    __syncthreads();
    int* fidx = (int*)zs;                   // final index per m-row
    if (tid < MT) {
        int m = tid;
        float bv = rv[m];
        int   bi = ri[m];
        #pragma unroll
        for (int t = 1; t < 16; t++) {
            float v = rv[t * 132 + m];
            int  id = ri[t * 132 + m];
            if (v < bv || (v == bv && id < bi)) { bv = v; bi = id; }
        }
        fidx[m] = bi;
    }
    __syncthreads();

    // --- gather + write output (codebook is L2-hot, 1 MB total) ---
    const float4* cb4 = (const float4*)cb;
    float4* out4 = (float4*)out;
    #pragma unroll
    for (int i = tid; i < MT * (DIM / 4); i += 256) {
        int m = i >> 5;                     // DIM/4 = 32 float4 per row
        int c = i & 31;
        int idx = fidx[m];
        out4[(size_t)(m0 + m) * 32 + c] = cb4[(size_t)idx * 32 + c];
    }
}

// ---------------------------------------------------------------------------
extern "C" void kernel_launch(void* const* d_in, const int* in_sizes, int n_in,
                              void* d_out, int out_size) {
    const float* ze = (const float*)d_in[0];   // [2048, 4096] == [65536, 128]
    const float* cb = (const float*)d_in[1];   // [2048, 128]
    float* out = (float*)d_out;                // [65536, 128]

    (void)in_sizes; (void)n_in; (void)out_size;

    cudaFuncSetAttribute(vq_kernel,
                         cudaFuncAttributeMaxDynamicSharedMemorySize,
                         131072);

    cnorm_kernel<<<KCB / 8, 256>>>(cb);
    vq_kernel<<<NWIN / MT, 256, 131072>>>(ze, cb, out);
}